// round 2
// baseline (speedup 1.0000x reference)
#include <cuda_runtime.h>
#include <cstdint>
#include <cstddef>

typedef unsigned long long ull;

// ---------------- constants ----------------
// B=256, S=512, D=200, H=256, 4 gates -> N=1024 packed gate columns
#define BB   256
#define SS   512
#define DD   200
#define HH   256
#define NJ   1024          // 4*H packed
#define NGRP 16            // batch groups (16 rows each)
#define NCOL 8             // column-group CTAs per batch group (32 hidden cols each)

// ---------------- device scratch (static: no cudaMalloc allowed) ----------------
__device__ float    g_G[134217728];   // [S][B][1024] gate preactivations (x part + bias), 536MB
__device__ float    g_Wxp[DD * NJ];   // packed x-weights  [200][1024]
__device__ float    g_Whp[8 * 32768]; // packed h-weights  [colgrp][256][128]
__device__ float    g_biasp[NJ];
__device__ float    g_hbuf[2 * BB * HH]; // double-buffered h mailbox
__device__ unsigned g_bar[NGRP];         // per-group monotonic barrier counters

// ---------------- helpers ----------------
__device__ __forceinline__ ull pk2(float lo, float hi) {
    ull r; asm("mov.b64 %0,{%1,%2};" : "=l"(r) : "f"(lo), "f"(hi)); return r;
}
__device__ __forceinline__ void upk2(ull v, float& lo, float& hi) {
    asm("mov.b64 {%0,%1},%2;" : "=f"(lo), "=f"(hi) : "l"(v));
}
__device__ __forceinline__ ull ffma2(ull a, ull b, ull c) {
    ull d; asm("fma.rn.f32x2 %0,%1,%2,%3;" : "=l"(d) : "l"(a), "l"(b), "l"(c)); return d;
}
__device__ __forceinline__ float sigf(float x) {
    return __fdividef(1.0f, 1.0f + __expf(-x));
}
__device__ __forceinline__ float tanhfast(float x) {
    return __fdividef(2.0f, 1.0f + __expf(-2.0f * x)) - 1.0f;
}
__device__ __forceinline__ unsigned ldspin(const unsigned* p) {
    unsigned v; asm volatile("ld.global.cg.u32 %0,[%1];" : "=r"(v) : "l"(p)); return v;
}

// ---------------- kernel 0: pack weights ----------------
// j = g*128 + c*4 + gate  (g: col group 0..7, c: col-in-group 0..31, gate: i,f,o,z)
__global__ void k_pack(const float* __restrict__ Wi, const float* __restrict__ Wf,
                       const float* __restrict__ Wo, const float* __restrict__ Wz,
                       const float* __restrict__ bi, const float* __restrict__ bf,
                       const float* __restrict__ bo, const float* __restrict__ bz) {
    int idx = blockIdx.x * blockDim.x + threadIdx.x;
    if (idx < 456 * NJ) {
        int k = idx >> 10;
        int j = idx & (NJ - 1);
        int gate = j & 3;
        int c    = (j >> 2) & 31;
        int g    = j >> 7;
        int col  = g * 32 + c;
        const float* W = (gate == 0) ? Wi : (gate == 1) ? Wf : (gate == 2) ? Wo : Wz;
        float v = W[k * HH + col];
        if (k < DD) g_Wxp[k * NJ + j] = v;
        else        g_Whp[g * 32768 + (k - DD) * 128 + (j & 127)] = v;
    }
    if (idx < NJ) {
        int gate = idx & 3;
        int c    = (idx >> 2) & 31;
        int g    = idx >> 7;
        int col  = g * 32 + c;
        const float* bb = (gate == 0) ? bi : (gate == 1) ? bf : (gate == 2) ? bo : bz;
        g_biasp[idx] = bb[col];
    }
}

// ---------------- kernel 1: reset mailbox + barrier counters ----------------
__global__ void k_reset() {
    int i = blockIdx.x * blockDim.x + threadIdx.x;
    if (i < 2 * BB * HH) g_hbuf[i] = 0.0f;
    if (i < NGRP)        g_bar[i] = 0u;
}

// ---------------- kernel 2: G = X @ Wxp + bias ----------------
// M = S*B = 131072 (m = s*256 + b), N = 1024, K = 200. Tile 128x64, K-chunk 8.
#define G1_BM 128
#define G1_BN 64
#define G1_BK 8
__global__ void __launch_bounds__(256, 1) k_gemm1(const float* __restrict__ x) {
    __shared__ float As[G1_BK][G1_BM];   // transposed A tile
    __shared__ float Bs[G1_BK][G1_BN];

    int tid = threadIdx.x;
    int m0 = blockIdx.y * G1_BM;
    int n0 = blockIdx.x * G1_BN;

    // A loader: 2 threads per row, each a float4 of k
    int arow = tid >> 1;
    int akq  = (tid & 1) * 4;
    int m    = m0 + arow;
    int b    = m & (BB - 1);
    int sidx = m >> 8;
    const float* aptr = x + ((size_t)b * SS + sidx) * DD + akq;

    // B loader: 32 threads per k-row, float2 each
    int bkk = tid >> 5;
    int bn  = (tid & 31) * 2;
    const float* bptr = g_Wxp + (size_t)bkk * NJ + n0 + bn;

    int tx = tid & 15;   // n sub-tile (4 cols)
    int ty = tid >> 4;   // m sub-tile (8 rows)

    ull acc[4][4];       // [row-pair][col], f32x2 packs 2 rows
#pragma unroll
    for (int i = 0; i < 4; ++i)
#pragma unroll
        for (int j = 0; j < 4; ++j) acc[i][j] = 0ull;

    for (int kc = 0; kc < 25; ++kc) {
        int k0 = kc * G1_BK;
        float4 av = *(const float4*)(aptr + k0);
        float2 bv = *(const float2*)(bptr + (size_t)k0 * NJ);
        __syncthreads();
        As[akq + 0][arow] = av.x;
        As[akq + 1][arow] = av.y;
        As[akq + 2][arow] = av.z;
        As[akq + 3][arow] = av.w;
        *(float2*)&Bs[bkk][bn] = bv;
        __syncthreads();
#pragma unroll
        for (int kk = 0; kk < G1_BK; ++kk) {
            const ull* ap2 = (const ull*)&As[kk][ty * 8];
            ull a0 = ap2[0], a1 = ap2[1], a2 = ap2[2], a3 = ap2[3];
            float4 b4 = *(const float4*)&Bs[kk][tx * 4];
            ull b0 = pk2(b4.x, b4.x), b1 = pk2(b4.y, b4.y);
            ull b2 = pk2(b4.z, b4.z), b3 = pk2(b4.w, b4.w);
            acc[0][0] = ffma2(a0, b0, acc[0][0]); acc[0][1] = ffma2(a0, b1, acc[0][1]);
            acc[0][2] = ffma2(a0, b2, acc[0][2]); acc[0][3] = ffma2(a0, b3, acc[0][3]);
            acc[1][0] = ffma2(a1, b0, acc[1][0]); acc[1][1] = ffma2(a1, b1, acc[1][1]);
            acc[1][2] = ffma2(a1, b2, acc[1][2]); acc[1][3] = ffma2(a1, b3, acc[1][3]);
            acc[2][0] = ffma2(a2, b0, acc[2][0]); acc[2][1] = ffma2(a2, b1, acc[2][1]);
            acc[2][2] = ffma2(a2, b2, acc[2][2]); acc[2][3] = ffma2(a2, b3, acc[2][3]);
            acc[3][0] = ffma2(a3, b0, acc[3][0]); acc[3][1] = ffma2(a3, b1, acc[3][1]);
            acc[3][2] = ffma2(a3, b2, acc[3][2]); acc[3][3] = ffma2(a3, b3, acc[3][3]);
        }
    }

    float4 bias4 = *(const float4*)(g_biasp + n0 + tx * 4);
#pragma unroll
    for (int rp = 0; rp < 4; ++rp) {
        float4 r0, r1;
        upk2(acc[rp][0], r0.x, r1.x);
        upk2(acc[rp][1], r0.y, r1.y);
        upk2(acc[rp][2], r0.z, r1.z);
        upk2(acc[rp][3], r0.w, r1.w);
        r0.x += bias4.x; r0.y += bias4.y; r0.z += bias4.z; r0.w += bias4.w;
        r1.x += bias4.x; r1.y += bias4.y; r1.z += bias4.z; r1.w += bias4.w;
        size_t mrow = (size_t)m0 + ty * 8 + rp * 2;
        *(float4*)(g_G + mrow * NJ + n0 + tx * 4)       = r0;
        *(float4*)(g_G + (mrow + 1) * NJ + n0 + tx * 4) = r1;
    }
}

// ---------------- kernel 3: persistent recurrence ----------------
// 128 CTAs = 16 batch groups x 8 col-group CTAs. Wh slice stays in smem.
#define REC_SMEM_BYTES ((32768 + 4096 + 8192) * 4)
__global__ void __launch_bounds__(256, 1) k_rec(const float* __restrict__ mask,
                                                float* __restrict__ out) {
    extern __shared__ float sm[];
    float* Ws = sm;             // [256][128] weight slice  (131072 B)
    float* hs = sm + 32768;     // [256 k][16 rows] h, transposed (16384 B)
    float* ms = sm + 36864;     // [16 rows][512 s] mask     (32768 B)

    int tid   = threadIdx.x;
    int group = blockIdx.x >> 3;
    int g     = blockIdx.x & 7;
    int row   = tid & 15;       // batch row within group
    int cp    = tid >> 4;       // column pair (2 hidden cols, 8 gate-cols)

    // preload weight slice (once for all 512 steps)
    {
        const float4* wsrc = (const float4*)(g_Whp + (size_t)g * 32768);
        float4* wdst = (float4*)Ws;
        for (int i = tid; i < 8192; i += 256) wdst[i] = wsrc[i];
    }
    // preload mask rows
    {
        for (int i = tid; i < 2048; i += 256) {
            int r = i >> 7, sc = i & 127;
            ((float4*)ms)[i] =
                ((const float4*)(mask + ((size_t)(group * 16 + r)) * SS))[sc];
        }
    }
    __syncthreads();

    int b = group * 16 + row;
    float c0 = 0.f, c1 = 0.f, s0 = 0.f, s1 = 0.f, msum = 0.f;
    int hq_r = tid & 15, hq_k = tid >> 4;

    for (int s = 0; s < SS; ++s) {
        // prefetch this step's x-gate preactivations (independent of h)
        const float4* gp =
            (const float4*)(g_G + (((size_t)s * BB + b) * NJ) + g * 128 + cp * 8);
        float4 ga = __ldcs(gp);
        float4 gb = __ldcs(gp + 1);
        float mval = ms[row * SS + s];

        // wait for all 8 CTAs of this group to finish step s-1
        if (s > 0) {
            if (tid == 0) {
                unsigned tgt = 8u * (unsigned)s;
                while (ldspin(&g_bar[group]) < tgt) __nanosleep(40);
            }
            __syncthreads();
        }

        // gather h[s] (16 rows x 256) into smem, transposed to [k][row]
        {
            const float4* src = (const float4*)(g_hbuf + ((size_t)(s & 1)) * (BB * HH) +
                                                ((size_t)(group * 16 + hq_r)) * HH +
                                                hq_k * 16);
            float4 v0 = __ldcg(src), v1 = __ldcg(src + 1);
            float4 v2 = __ldcg(src + 2), v3 = __ldcg(src + 3);
            int kb = hq_k * 16;
            hs[(kb + 0) * 16 + hq_r] = v0.x;  hs[(kb + 1) * 16 + hq_r] = v0.y;
            hs[(kb + 2) * 16 + hq_r] = v0.z;  hs[(kb + 3) * 16 + hq_r] = v0.w;
            hs[(kb + 4) * 16 + hq_r] = v1.x;  hs[(kb + 5) * 16 + hq_r] = v1.y;
            hs[(kb + 6) * 16 + hq_r] = v1.z;  hs[(kb + 7) * 16 + hq_r] = v1.w;
            hs[(kb + 8) * 16 + hq_r] = v2.x;  hs[(kb + 9) * 16 + hq_r] = v2.y;
            hs[(kb + 10) * 16 + hq_r] = v2.z; hs[(kb + 11) * 16 + hq_r] = v2.w;
            hs[(kb + 12) * 16 + hq_r] = v3.x; hs[(kb + 13) * 16 + hq_r] = v3.y;
            hs[(kb + 14) * 16 + hq_r] = v3.z; hs[(kb + 15) * 16 + hq_r] = v3.w;
        }
        __syncthreads();

        // gates = G + h @ Wh  (thread: 1 row x 8 gate-cols)
        ull acc0 = pk2(ga.x, ga.y), acc1 = pk2(ga.z, ga.w);
        ull acc2 = pk2(gb.x, gb.y), acc3 = pk2(gb.z, gb.w);
        const float* wbase = Ws + cp * 8;
#pragma unroll 8
        for (int k = 0; k < HH; ++k) {
            float hk = hs[k * 16 + row];
            ull h2 = pk2(hk, hk);
            const ulonglong2* wp = (const ulonglong2*)(wbase + k * 128);
            ulonglong2 wa = wp[0], wb2 = wp[1];
            acc0 = ffma2(h2, wa.x, acc0);
            acc1 = ffma2(h2, wa.y, acc1);
            acc2 = ffma2(h2, wb2.x, acc2);
            acc3 = ffma2(h2, wb2.y, acc3);
        }

        // nonlinearity + state update (gate order i,f,o,z)
        float ai0, af0, ao0, az0, ai1, af1, ao1, az1;
        upk2(acc0, ai0, af0); upk2(acc1, ao0, az0);
        upk2(acc2, ai1, af1); upk2(acc3, ao1, az1);
        float i0 = sigf(ai0), f0 = sigf(af0), o0 = sigf(ao0), z0 = tanhfast(az0);
        c0 = i0 * z0 + f0 * c0;
        float h0 = o0 * tanhfast(c0);
        float i1 = sigf(ai1), f1 = sigf(af1), o1 = sigf(ao1), z1 = tanhfast(az1);
        c1 = i1 * z1 + f1 * c1;
        float h1 = o1 * tanhfast(c1);
        s0 += h0 * mval; s1 += h1 * mval; msum += mval;

        // publish h[s+1] to the mailbox
        float2 hv; hv.x = h0; hv.y = h1;
        __stcg((float2*)(g_hbuf + ((size_t)((s + 1) & 1)) * (BB * HH) +
                         (size_t)b * HH + g * 32 + cp * 2), hv);
        __threadfence();
        __syncthreads();
        if (tid == 0) atomicAdd(&g_bar[group], 1u);
    }

    float inv = __fdividef(1.0f, msum);
    out[(size_t)b * HH + g * 32 + cp * 2]     = s0 * inv;
    out[(size_t)b * HH + g * 32 + cp * 2 + 1] = s1 * inv;
}

// ---------------- launcher ----------------
extern "C" void kernel_launch(void* const* d_in, const int* in_sizes, int n_in,
                              void* d_out, int out_size) {
    const float* x    = (const float*)d_in[0];
    const float* mask = (const float*)d_in[1];
    const float* Wi   = (const float*)d_in[2];
    const float* bi   = (const float*)d_in[3];
    const float* Wf   = (const float*)d_in[4];
    const float* bf   = (const float*)d_in[5];
    const float* Wo   = (const float*)d_in[6];
    const float* bo   = (const float*)d_in[7];
    const float* Wz   = (const float*)d_in[8];
    const float* bz   = (const float*)d_in[9];
    float* out = (float*)d_out;

    cudaFuncSetAttribute(k_rec, cudaFuncAttributeMaxDynamicSharedMemorySize,
                         REC_SMEM_BYTES);

    k_pack<<<(456 * NJ + 255) / 256, 256>>>(Wi, Wf, Wo, Wz, bi, bf, bo, bz);
    k_reset<<<512, 256>>>();
    dim3 g1(NJ / G1_BN, (SS * BB) / G1_BM);
    k_gemm1<<<g1, 256>>>(x);
    k_rec<<<NGRP * NCOL, 256, REC_SMEM_BYTES>>>(mask, out);
}